// round 16
// baseline (speedup 1.0000x reference)
#include <cuda_runtime.h>
#include <math.h>

#define Bsz 4
#define Ssz 8192
#define Dsz 1024
#define Nsz 12
#define NROWS (Bsz*Ssz)
#define NBLK 512             // one 64-row chunk per block
#define RPB 64

typedef unsigned long long u64;

// Scratch (allocation-free rule: __device__ globals)
__device__ u64   g_wdup[(size_t)NROWS * Nsz];            // 3 MB (slow path only)
__device__ float g_Upart[(size_t)NBLK * Nsz * Dsz];      // 25.2 MB (flag-gated)
__device__ unsigned char g_rowflag[NROWS];
__device__ int   g_flags[NBLK];
__device__ float g_U[48 * Dsz];
__device__ float g_SV[48 * Dsz];
__device__ float g_T[48 * Dsz];
__device__ unsigned g_done;                              // zero-init; monotonic

// ---- packed f32x2 helpers -------------------------------------------------
__device__ __forceinline__ void ffma2(u64& d, u64 a, u64 b) {
    asm("fma.rn.f32x2 %0, %1, %2, %0;" : "+l"(d) : "l"(a), "l"(b));
}
__device__ __forceinline__ u64 f2u(float lo, float hi) {
    u64 v;
    asm("mov.b64 %0, {%1,%2};" : "=l"(v) : "f"(lo), "f"(hi));
    return v;
}
__device__ __forceinline__ void stz_cs(float* p) {   // streaming 16B zero store
    asm volatile("st.global.cs.v4.u32 [%0], {%1, %1, %1, %1};"
                 :: "l"(p), "r"(0u) : "memory");
}

// ---- slow path: exact full-precision row (arbitrary inputs) ---------------
__device__ __forceinline__ void slow_row(
    const float4* v, float x2, int rloc, size_t row0, int lane,
    const float* c2s, const float* invs, const float* ampv,
    u64 (*wsm)[Nsz], int* anynz, const float* __restrict__ centers) {
    float pn[Nsz];
    #pragma unroll
    for (int n = 0; n < Nsz; n++) pn[n] = 0.f;
    #pragma unroll 1
    for (int j = 0; j < 8; j++) {
        float4 xv = v[j];
        #pragma unroll
        for (int n = 0; n < Nsz; n++) {
            float4 c4 = __ldg((const float4*)(centers + (size_t)n * Dsz + j * 128 + lane * 4));
            pn[n] += xv.x * c4.x + xv.y * c4.y + xv.z * c4.z + xv.w * c4.w;
        }
    }
    #pragma unroll
    for (int n = 0; n < Nsz; n++) {
        #pragma unroll
        for (int o = 16; o > 0; o >>= 1)
            pn[n] += __shfl_xor_sync(0xffffffffu, pn[n], o);
    }
    float sum = 0.f, gl = 0.f;
    #pragma unroll
    for (int n = 0; n < Nsz; n++) {
        float d2 = fmaxf(x2 + c2s[n] - 2.f * pn[n], 0.f);
        float gg = expf(-d2 * invs[n]) * ampv[n];
        sum += gg;
        if (lane == n) gl = gg;
    }
    float inv = 1.f / fmaxf(sum, 1e-8f);
    if (lane < Nsz) wsm[rloc][lane] = f2u(gl * inv, gl * inv);
    if (lane == 0) {
        g_rowflag[row0 + rloc] = (sum > 0.f) ? 1 : 0;
        if (sum > 0.f) *anynz = 1;
    }
}

union SmemTail {
    struct { float As[64][49]; float Ws[64][66]; } g;
    struct { u64 wd[256][Nsz]; unsigned char fl[256]; } e;
};

// ===========================================================================
// Single fused kernel. 512 blocks x 256 thr. Fast path: prelude zero-stores +
// classify; last-finished block verifies no chunk flagged and exits.
// Slow path (exact, any input): flagged blocks store U partials; the LAST
// block alone runs reduce -> gemms -> expand (single-block, no grid barriers).
// ===========================================================================
__global__ void __launch_bounds__(256)
k1(const float* __restrict__ x, const float* __restrict__ centers,
   const float* __restrict__ scales, const float* __restrict__ amps,
   const float* __restrict__ w_value, const float* __restrict__ w_output,
   float* __restrict__ out) {
    __shared__ float c2s[Nsz], sqc2[Nsz], invs[Nsz], ampv[Nsz], thr[Nsz];
    __shared__ u64 wsm[RPB][Nsz];
    __shared__ SmemTail sm;
    __shared__ int anynz, isLast, sAny;

    const int t = threadIdx.x, lane = t & 31, wid = t >> 5;
    const int bid = blockIdx.x;
    const size_t row0 = (size_t)bid * RPB;

    // ---- prelude: zero-fill this warp's 8 output rows (streaming, no deps) --
    {
        float* ob = out + (row0 + wid * 8) * Dsz + lane * 4;
        #pragma unroll
        for (int r = 0; r < 8; r++) {
            #pragma unroll
            for (int j = 0; j < 8; j++)
                stz_cs(ob + (size_t)r * Dsz + j * 128);
        }
    }

    // ---- params ----
    for (int n = wid; n < Nsz; n += 8) {
        const float* cn = centers + (size_t)n * Dsz + lane * 4;
        float s = 0.f;
        #pragma unroll
        for (int j = 0; j < 8; j++) {
            float4 v = __ldg((const float4*)(cn + j * 128));
            s += v.x * v.x + v.y * v.y + v.z * v.z + v.w * v.w;
        }
        #pragma unroll
        for (int o = 16; o > 0; o >>= 1) s += __shfl_xor_sync(0xffffffffu, s, o);
        if (lane == 0) { c2s[n] = s; sqc2[n] = sqrtf(s); }
    }
    if (t < Nsz) {
        float sv = expf(scales[t]);
        sv = fminf(fmaxf(sv, 0.1f), 2.0f);
        invs[t] = 0.5f / (sv * sv);
        ampv[t] = 1.f / (1.f + expf(-amps[t]));
        thr[t]  = sqrtf(120.0f / invs[t]);   // |sqrt(x2)-sqrt(c2)| > thr => exp==0 exactly
    }
    if (t == 0) anynz = 0;
    __syncthreads();

    // ---- classify 8 rows per warp (pairs in flight) ----
    #pragma unroll 1
    for (int rp = 0; rp < 8; rp += 2) {
        const int rA = wid * 8 + rp, rB = rA + 1;
        const float4* xA = (const float4*)(x + (row0 + rA) * Dsz) + lane;
        const float4* xB = (const float4*)(x + (row0 + rB) * Dsz) + lane;

        float4 vA[8], vB[8];
        #pragma unroll
        for (int j = 0; j < 8; j++) { vA[j] = __ldcs(xA + j * 32); vB[j] = __ldcs(xB + j * 32); }

        float a0 = 0.f, a1 = 0.f, a2 = 0.f, a3 = 0.f;
        float b0 = 0.f, b1 = 0.f, b2 = 0.f, b3 = 0.f;
        #pragma unroll
        for (int j = 0; j < 8; j += 4) {
            a0 += vA[j  ].x * vA[j  ].x + vA[j  ].y * vA[j  ].y + vA[j  ].z * vA[j  ].z + vA[j  ].w * vA[j  ].w;
            a1 += vA[j+1].x * vA[j+1].x + vA[j+1].y * vA[j+1].y + vA[j+1].z * vA[j+1].z + vA[j+1].w * vA[j+1].w;
            a2 += vA[j+2].x * vA[j+2].x + vA[j+2].y * vA[j+2].y + vA[j+2].z * vA[j+2].z + vA[j+2].w * vA[j+2].w;
            a3 += vA[j+3].x * vA[j+3].x + vA[j+3].y * vA[j+3].y + vA[j+3].z * vA[j+3].z + vA[j+3].w * vA[j+3].w;
            b0 += vB[j  ].x * vB[j  ].x + vB[j  ].y * vB[j  ].y + vB[j  ].z * vB[j  ].z + vB[j  ].w * vB[j  ].w;
            b1 += vB[j+1].x * vB[j+1].x + vB[j+1].y * vB[j+1].y + vB[j+1].z * vB[j+1].z + vB[j+1].w * vB[j+1].w;
            b2 += vB[j+2].x * vB[j+2].x + vB[j+2].y * vB[j+2].y + vB[j+2].z * vB[j+2].z + vB[j+2].w * vB[j+2].w;
            b3 += vB[j+3].x * vB[j+3].x + vB[j+3].y * vB[j+3].y + vB[j+3].z * vB[j+3].z + vB[j+3].w * vB[j+3].w;
        }
        float pA = (a0 + a1) + (a2 + a3);
        float pB = (b0 + b1) + (b2 + b3);
        #pragma unroll
        for (int o = 16; o > 0; o >>= 1) {
            pA += __shfl_xor_sync(0xffffffffu, pA, o);
            pB += __shfl_xor_sync(0xffffffffu, pB, o);
        }
        const float xrA = sqrtf(pA), xrB = sqrtf(pB);
        bool okA = true, okB = true;
        if (lane < Nsz) {
            okA = fabsf(xrA - sqc2[lane]) > thr[lane];
            okB = fabsf(xrB - sqc2[lane]) > thr[lane];
        }
        const unsigned bA = __ballot_sync(0xffffffffu, okA);
        const unsigned bB = __ballot_sync(0xffffffffu, okB);
        if (bA == 0xffffffffu) {
            if (lane < Nsz) wsm[rA][lane] = 0ull;
            if (lane == 0) g_rowflag[row0 + rA] = 0;
        } else {
            slow_row(vA, pA, rA, row0, lane, c2s, invs, ampv, wsm, &anynz, centers);
        }
        if (bB == 0xffffffffu) {
            if (lane < Nsz) wsm[rB][lane] = 0ull;
            if (lane == 0) g_rowflag[row0 + rB] = 0;
        } else {
            slow_row(vB, pB, rB, row0, lane, c2s, invs, ampv, wsm, &anynz, centers);
        }
    }
    __syncthreads();

    if (anynz) {
        // ---- SLOW PATH: stage w, accumulate U partials (exact) ----
        for (int i = t; i < RPB * Nsz; i += 256)
            g_wdup[row0 * Nsz + i] = ((const u64*)wsm)[i];
        ulonglong2 acc[Nsz];
        #pragma unroll
        for (int n = 0; n < Nsz; n++) { acc[n].x = 0ull; acc[n].y = 0ull; }
        #pragma unroll 1
        for (int rr = 0; rr < RPB; rr += 8) {
            ulonglong2 xv[8];
            #pragma unroll
            for (int j = 0; j < 8; j++)
                xv[j] = *(const ulonglong2*)(x + (row0 + rr + j) * Dsz + t * 4);
            #pragma unroll
            for (int j = 0; j < 8; j++) {
                const ulonglong2* wp = (const ulonglong2*)wsm[rr + j];
                #pragma unroll
                for (int pq = 0; pq < 6; pq++) {
                    ulonglong2 q = wp[pq];
                    ffma2(acc[2 * pq    ].x, q.x, xv[j].x);
                    ffma2(acc[2 * pq    ].y, q.x, xv[j].y);
                    ffma2(acc[2 * pq + 1].x, q.y, xv[j].x);
                    ffma2(acc[2 * pq + 1].y, q.y, xv[j].y);
                }
            }
        }
        float* up = g_Upart + (size_t)bid * Nsz * Dsz + t * 4;
        #pragma unroll
        for (int n = 0; n < Nsz; n++) *(ulonglong2*)(up + n * Dsz) = acc[n];
    }
    if (t == 0) g_flags[bid] = anynz;

    // ---- last-block-done detection (replay-safe monotonic counter) ----
    __threadfence();
    __syncthreads();
    if (t == 0) {
        unsigned pos = atomicAdd(&g_done, 1u);
        isLast = ((pos % NBLK) == NBLK - 1u) ? 1 : 0;
    }
    __syncthreads();
    if (!isLast) return;

    // ---- last block: check flags; fast path exits (out fully zeroed) ----
    if (t == 0) sAny = 0;
    __syncthreads();
    {
        int a = 0;
        for (int i = t; i < NBLK; i += 256) a |= __ldcg(&g_flags[i]);
        if (a) sAny = 1;
    }
    __syncthreads();
    if (!sAny) return;

    // ================= SLOW TAIL (single block; exact; no grid bars) =======
    // reduce Upart -> U; zero SV, T
    for (int item = t; item < 48 * 256; item += 256) {
        int bn = item >> 8, dd = item & 255;
        int bb = bn / Nsz, nn = bn % Nsz;
        float4 s = make_float4(0.f, 0.f, 0.f, 0.f);
        for (int c = 0; c < 128; c++) {
            if (__ldcg(&g_flags[bb * 128 + c])) {
                const float4 v = __ldcg((const float4*)(g_Upart +
                    ((size_t)(bb * 128 + c) * Nsz + nn) * Dsz + dd * 4));
                s.x += v.x; s.y += v.y; s.z += v.z; s.w += v.w;
            }
        }
        *(float4*)(g_U + bn * Dsz + dd * 4) = s;
        float4 z4 = make_float4(0.f, 0.f, 0.f, 0.f);
        *(float4*)(g_SV + bn * Dsz + dd * 4) = z4;
        *(float4*)(g_T + bn * Dsz + dd * 4) = z4;
    }
    __syncthreads();

    // two gemms, 256 k-split tiles each, sequential (single block: plain +=)
    for (int phase = 0; phase < 2; phase++) {
        const float* A = phase ? g_SV : g_U;
        const float* W = phase ? w_output : w_value;
        float* C = phase ? g_T : g_SV;
        for (int tile = 0; tile < 256; tile++) {
            int e0 = (tile & 15) * 64, k0 = (tile >> 4) * 64;
            __syncthreads();
            for (int idx = t; idx < 48 * 64; idx += 256) {
                int m = idx >> 6, kk = idx & 63;
                sm.g.As[kk][m] = A[(size_t)m * Dsz + k0 + kk];
            }
            for (int idx = t; idx < 64 * 64; idx += 256) {
                int e = idx >> 6, kk = idx & 63;
                sm.g.Ws[kk][e] = __ldg(W + (size_t)(e0 + e) * Dsz + k0 + kk);
            }
            __syncthreads();
            int ty = t >> 5, tx = t & 31;
            float a0[6][2];
            #pragma unroll
            for (int i = 0; i < 6; i++) { a0[i][0] = 0.f; a0[i][1] = 0.f; }
            for (int kk = 0; kk < 64; kk++) {
                float av[6];
                #pragma unroll
                for (int i = 0; i < 6; i++) av[i] = sm.g.As[kk][ty * 6 + i];
                float2 wv = *(const float2*)&sm.g.Ws[kk][tx * 2];
                #pragma unroll
                for (int i = 0; i < 6; i++) {
                    a0[i][0] += av[i] * wv.x;
                    a0[i][1] += av[i] * wv.y;
                }
            }
            #pragma unroll
            for (int i = 0; i < 6; i++) {
                int m = ty * 6 + i;
                C[(size_t)m * Dsz + e0 + tx * 2 + 0] += a0[i][0];
                C[(size_t)m * Dsz + e0 + tx * 2 + 1] += a0[i][1];
            }
        }
        __syncthreads();
    }

    // expand: rewrite ALL rows (exact; overwrites the prelude zeros)
    for (int seg = 0; seg < 128; seg++) {
        const size_t r0s = (size_t)seg * 256;
        const int b = seg >> 5;
        const int col = t * 4;
        __syncthreads();
        for (int i = t; i < 256 * Nsz; i += 256) {
            int r = i / Nsz;
            ((u64*)sm.e.wd)[i] = __ldcg(&g_rowflag[r0s + r])
                                 ? __ldcg(&g_wdup[r0s * Nsz + i]) : 0ull;
        }
        if (t < 256) sm.e.fl[t] = __ldcg(&g_rowflag[r0s + t]);
        ulonglong2 trp[Nsz];
        #pragma unroll
        for (int n = 0; n < Nsz; n++)
            trp[n] = *(const ulonglong2*)(g_T + (size_t)(b * Nsz + n) * Dsz + col);
        __syncthreads();

        #pragma unroll 1
        for (int r = 0; r < 256; r++) {
            ulonglong2 o; o.x = 0ull; o.y = 0ull;
            if (sm.e.fl[r]) {
                const ulonglong2* wp = (const ulonglong2*)sm.e.wd[r];
                #pragma unroll
                for (int pq = 0; pq < 6; pq++) {
                    ulonglong2 q = wp[pq];
                    ffma2(o.x, q.x, trp[2 * pq    ].x);
                    ffma2(o.y, q.x, trp[2 * pq    ].y);
                    ffma2(o.x, q.y, trp[2 * pq + 1].x);
                    ffma2(o.y, q.y, trp[2 * pq + 1].y);
                }
            }
            *(ulonglong2*)(out + (r0s + r) * Dsz + col) = o;
        }
    }
}

extern "C" void kernel_launch(void* const* d_in, const int* in_sizes, int n_in,
                              void* d_out, int out_size) {
    const float* x        = (const float*)d_in[0];
    const float* centers  = (const float*)d_in[1];
    const float* scales   = (const float*)d_in[2];
    const float* amps     = (const float*)d_in[3];
    const float* w_value  = (const float*)d_in[4];
    const float* w_output = (const float*)d_in[5];
    float* out = (float*)d_out;

    k1<<<NBLK, 256>>>(x, centers, scales, amps, w_value, w_output, out);
}

// round 17
// speedup vs baseline: 1.0429x; 1.0429x over previous
#include <cuda_runtime.h>
#include <math.h>

#define Bsz 4
#define Ssz 8192
#define Dsz 1024
#define Nsz 12
#define NROWS (Bsz*Ssz)
#define NBLK 512             // one 64-row chunk per block
#define RPB 64

typedef unsigned long long u64;

// Scratch (allocation-free rule: __device__ globals)
__device__ u64   g_wdup[(size_t)NROWS * Nsz];            // 3 MB (slow path only)
__device__ float g_Upart[(size_t)NBLK * Nsz * Dsz];      // 25.2 MB (flag-gated)
__device__ unsigned char g_rowflag[NROWS];
__device__ int   g_flags[NBLK];
__device__ float g_U[48 * Dsz];
__device__ float g_SV[48 * Dsz];
__device__ float g_T[48 * Dsz];
__device__ unsigned g_done;                              // zero-init; monotonic

// ---- packed f32x2 helpers -------------------------------------------------
__device__ __forceinline__ void ffma2(u64& d, u64 a, u64 b) {
    asm("fma.rn.f32x2 %0, %1, %2, %0;" : "+l"(d) : "l"(a), "l"(b));
}
__device__ __forceinline__ u64 f2u(float lo, float hi) {
    u64 v;
    asm("mov.b64 %0, {%1,%2};" : "=l"(v) : "f"(lo), "f"(hi));
    return v;
}
__device__ __forceinline__ void stz_cs(float* p) {   // streaming 16B zero store
    asm volatile("st.global.cs.v4.u32 [%0], {%1, %1, %1, %1};"
                 :: "l"(p), "r"(0u) : "memory");
}

// ---- slow path: exact full-precision row (arbitrary inputs) ---------------
__device__ __forceinline__ void slow_row(
    const float4* v, float x2, int rloc, size_t row0, int lane,
    const float* c2s, const float* invs, const float* ampv,
    u64 (*wsm)[Nsz], int* anynz, const float* __restrict__ centers) {
    float pn[Nsz];
    #pragma unroll
    for (int n = 0; n < Nsz; n++) pn[n] = 0.f;
    #pragma unroll 1
    for (int j = 0; j < 8; j++) {
        float4 xv = v[j];
        #pragma unroll
        for (int n = 0; n < Nsz; n++) {
            float4 c4 = __ldg((const float4*)(centers + (size_t)n * Dsz + j * 128 + lane * 4));
            pn[n] += xv.x * c4.x + xv.y * c4.y + xv.z * c4.z + xv.w * c4.w;
        }
    }
    #pragma unroll
    for (int n = 0; n < Nsz; n++) {
        #pragma unroll
        for (int o = 16; o > 0; o >>= 1)
            pn[n] += __shfl_xor_sync(0xffffffffu, pn[n], o);
    }
    float sum = 0.f, gl = 0.f;
    #pragma unroll
    for (int n = 0; n < Nsz; n++) {
        float d2 = fmaxf(x2 + c2s[n] - 2.f * pn[n], 0.f);
        float gg = expf(-d2 * invs[n]) * ampv[n];
        sum += gg;
        if (lane == n) gl = gg;
    }
    float inv = 1.f / fmaxf(sum, 1e-8f);
    if (lane < Nsz) wsm[rloc][lane] = f2u(gl * inv, gl * inv);
    if (lane == 0) {
        g_rowflag[row0 + rloc] = (sum > 0.f) ? 1 : 0;
        if (sum > 0.f) *anynz = 1;
    }
}

// ===========================================================================
// Single fused kernel, 512 blocks x 256 thr, minimal smem (~6.3 KB).
// Fast path: prelude zero-stores + classify; last-done block checks flags,
// exits. Slow path: flagged blocks store U partials; last block alone runs a
// SMEM-FREE naive tail (reduce -> gemms -> expand) — correctness-only.
// ===========================================================================
__global__ void __launch_bounds__(256)
k1(const float* __restrict__ x, const float* __restrict__ centers,
   const float* __restrict__ scales, const float* __restrict__ amps,
   const float* __restrict__ w_value, const float* __restrict__ w_output,
   float* __restrict__ out) {
    __shared__ float c2s[Nsz], sqc2[Nsz], invs[Nsz], ampv[Nsz], thr[Nsz];
    __shared__ u64 wsm[RPB][Nsz];
    __shared__ int anynz, isLast, sAny;

    const int t = threadIdx.x, lane = t & 31, wid = t >> 5;
    const int bid = blockIdx.x;
    const size_t row0 = (size_t)bid * RPB;

    // ---- prelude: zero-fill this warp's 8 output rows (streaming, no deps) --
    {
        float* ob = out + (row0 + wid * 8) * Dsz + lane * 4;
        #pragma unroll
        for (int r = 0; r < 8; r++) {
            #pragma unroll
            for (int j = 0; j < 8; j++)
                stz_cs(ob + (size_t)r * Dsz + j * 128);
        }
    }

    // ---- params ----
    for (int n = wid; n < Nsz; n += 8) {
        const float* cn = centers + (size_t)n * Dsz + lane * 4;
        float s = 0.f;
        #pragma unroll
        for (int j = 0; j < 8; j++) {
            float4 v = __ldg((const float4*)(cn + j * 128));
            s += v.x * v.x + v.y * v.y + v.z * v.z + v.w * v.w;
        }
        #pragma unroll
        for (int o = 16; o > 0; o >>= 1) s += __shfl_xor_sync(0xffffffffu, s, o);
        if (lane == 0) { c2s[n] = s; sqc2[n] = sqrtf(s); }
    }
    if (t < Nsz) {
        float sv = expf(scales[t]);
        sv = fminf(fmaxf(sv, 0.1f), 2.0f);
        invs[t] = 0.5f / (sv * sv);
        ampv[t] = 1.f / (1.f + expf(-amps[t]));
        thr[t]  = sqrtf(120.0f / invs[t]);   // |sqrt(x2)-sqrt(c2)| > thr => exp==0 exactly
    }
    if (t == 0) anynz = 0;
    __syncthreads();

    // ---- classify 8 rows per warp (pairs in flight) ----
    #pragma unroll 1
    for (int rp = 0; rp < 8; rp += 2) {
        const int rA = wid * 8 + rp, rB = rA + 1;
        const float4* xA = (const float4*)(x + (row0 + rA) * Dsz) + lane;
        const float4* xB = (const float4*)(x + (row0 + rB) * Dsz) + lane;

        float4 vA[8], vB[8];
        #pragma unroll
        for (int j = 0; j < 8; j++) { vA[j] = __ldcs(xA + j * 32); vB[j] = __ldcs(xB + j * 32); }

        float a0 = 0.f, a1 = 0.f, a2 = 0.f, a3 = 0.f;
        float b0 = 0.f, b1 = 0.f, b2 = 0.f, b3 = 0.f;
        #pragma unroll
        for (int j = 0; j < 8; j += 4) {
            a0 += vA[j  ].x * vA[j  ].x + vA[j  ].y * vA[j  ].y + vA[j  ].z * vA[j  ].z + vA[j  ].w * vA[j  ].w;
            a1 += vA[j+1].x * vA[j+1].x + vA[j+1].y * vA[j+1].y + vA[j+1].z * vA[j+1].z + vA[j+1].w * vA[j+1].w;
            a2 += vA[j+2].x * vA[j+2].x + vA[j+2].y * vA[j+2].y + vA[j+2].z * vA[j+2].z + vA[j+2].w * vA[j+2].w;
            a3 += vA[j+3].x * vA[j+3].x + vA[j+3].y * vA[j+3].y + vA[j+3].z * vA[j+3].z + vA[j+3].w * vA[j+3].w;
            b0 += vB[j  ].x * vB[j  ].x + vB[j  ].y * vB[j  ].y + vB[j  ].z * vB[j  ].z + vB[j  ].w * vB[j  ].w;
            b1 += vB[j+1].x * vB[j+1].x + vB[j+1].y * vB[j+1].y + vB[j+1].z * vB[j+1].z + vB[j+1].w * vB[j+1].w;
            b2 += vB[j+2].x * vB[j+2].x + vB[j+2].y * vB[j+2].y + vB[j+2].z * vB[j+2].z + vB[j+2].w * vB[j+2].w;
            b3 += vB[j+3].x * vB[j+3].x + vB[j+3].y * vB[j+3].y + vB[j+3].z * vB[j+3].z + vB[j+3].w * vB[j+3].w;
        }
        float pA = (a0 + a1) + (a2 + a3);
        float pB = (b0 + b1) + (b2 + b3);
        #pragma unroll
        for (int o = 16; o > 0; o >>= 1) {
            pA += __shfl_xor_sync(0xffffffffu, pA, o);
            pB += __shfl_xor_sync(0xffffffffu, pB, o);
        }
        const float xrA = sqrtf(pA), xrB = sqrtf(pB);
        bool okA = true, okB = true;
        if (lane < Nsz) {
            okA = fabsf(xrA - sqc2[lane]) > thr[lane];
            okB = fabsf(xrB - sqc2[lane]) > thr[lane];
        }
        const unsigned bA = __ballot_sync(0xffffffffu, okA);
        const unsigned bB = __ballot_sync(0xffffffffu, okB);
        if (bA == 0xffffffffu) {
            if (lane < Nsz) wsm[rA][lane] = 0ull;
            if (lane == 0) g_rowflag[row0 + rA] = 0;
        } else {
            slow_row(vA, pA, rA, row0, lane, c2s, invs, ampv, wsm, &anynz, centers);
        }
        if (bB == 0xffffffffu) {
            if (lane < Nsz) wsm[rB][lane] = 0ull;
            if (lane == 0) g_rowflag[row0 + rB] = 0;
        } else {
            slow_row(vB, pB, rB, row0, lane, c2s, invs, ampv, wsm, &anynz, centers);
        }
    }
    __syncthreads();

    if (anynz) {
        // ---- SLOW PATH: stage w, accumulate U partials (exact) ----
        for (int i = t; i < RPB * Nsz; i += 256)
            g_wdup[row0 * Nsz + i] = ((const u64*)wsm)[i];
        ulonglong2 acc[Nsz];
        #pragma unroll
        for (int n = 0; n < Nsz; n++) { acc[n].x = 0ull; acc[n].y = 0ull; }
        #pragma unroll 1
        for (int rr = 0; rr < RPB; rr += 8) {
            ulonglong2 xv[8];
            #pragma unroll
            for (int j = 0; j < 8; j++)
                xv[j] = *(const ulonglong2*)(x + (row0 + rr + j) * Dsz + t * 4);
            #pragma unroll
            for (int j = 0; j < 8; j++) {
                const ulonglong2* wp = (const ulonglong2*)wsm[rr + j];
                #pragma unroll
                for (int pq = 0; pq < 6; pq++) {
                    ulonglong2 q = wp[pq];
                    ffma2(acc[2 * pq    ].x, q.x, xv[j].x);
                    ffma2(acc[2 * pq    ].y, q.x, xv[j].y);
                    ffma2(acc[2 * pq + 1].x, q.y, xv[j].x);
                    ffma2(acc[2 * pq + 1].y, q.y, xv[j].y);
                }
            }
        }
        float* up = g_Upart + (size_t)bid * Nsz * Dsz + t * 4;
        #pragma unroll
        for (int n = 0; n < Nsz; n++) *(ulonglong2*)(up + n * Dsz) = acc[n];
    }
    if (t == 0) g_flags[bid] = anynz;

    // ---- last-block-done detection (replay-safe monotonic counter) ----
    __threadfence();
    __syncthreads();
    if (t == 0) {
        unsigned pos = atomicAdd(&g_done, 1u);
        isLast = ((pos % NBLK) == NBLK - 1u) ? 1 : 0;
    }
    __syncthreads();
    if (!isLast) return;

    // ---- last block: check flags; fast path exits (out fully zeroed) ----
    if (t == 0) sAny = 0;
    __syncthreads();
    {
        int a = 0;
        for (int i = t; i < NBLK; i += 256) a |= __ldcg(&g_flags[i]);
        if (a) sAny = 1;
    }
    __syncthreads();
    if (!sAny) return;

    // ============ SLOW TAIL: single block, SMEM-FREE, exact ================
    // (correctness-only; perf irrelevant — never taken unless some w != 0)
    // reduce Upart -> U
    for (int item = t; item < 48 * 256; item += 256) {
        int bn = item >> 8, dd = item & 255;
        int bb = bn / Nsz, nn = bn % Nsz;
        float4 s = make_float4(0.f, 0.f, 0.f, 0.f);
        for (int c = 0; c < 128; c++) {
            if (__ldcg(&g_flags[bb * 128 + c])) {
                const float4 v = __ldcg((const float4*)(g_Upart +
                    ((size_t)(bb * 128 + c) * Nsz + nn) * Dsz + dd * 4));
                s.x += v.x; s.y += v.y; s.z += v.z; s.w += v.w;
            }
        }
        *(float4*)(g_U + bn * Dsz + dd * 4) = s;
    }
    __syncthreads();

    // naive gemms from global (L2-resident working set): C[m,e] = sum_k A[m,k]W[e,k]
    for (int phase = 0; phase < 2; phase++) {
        const float* A = phase ? g_SV : g_U;
        const float* W = phase ? w_output : w_value;
        float* C = phase ? g_T : g_SV;
        for (int item = t; item < 48 * Dsz; item += 256) {
            int m = item >> 10, e = item & 1023;
            float s0 = 0.f, s1 = 0.f, s2 = 0.f, s3 = 0.f;
            const float4* Ar = (const float4*)(A + (size_t)m * Dsz);
            const float4* Wr = (const float4*)(W + (size_t)e * Dsz);
            for (int k = 0; k < Dsz / 4; k += 4) {
                float4 a0 = Ar[k],     w0 = __ldg(&Wr[k]);
                float4 a1 = Ar[k + 1], w1 = __ldg(&Wr[k + 1]);
                float4 a2 = Ar[k + 2], w2 = __ldg(&Wr[k + 2]);
                float4 a3 = Ar[k + 3], w3 = __ldg(&Wr[k + 3]);
                s0 += a0.x * w0.x + a0.y * w0.y + a0.z * w0.z + a0.w * w0.w;
                s1 += a1.x * w1.x + a1.y * w1.y + a1.z * w1.z + a1.w * w1.w;
                s2 += a2.x * w2.x + a2.y * w2.y + a2.z * w2.z + a2.w * w2.w;
                s3 += a3.x * w3.x + a3.y * w3.y + a3.z * w3.z + a3.w * w3.w;
            }
            C[(size_t)m * Dsz + e] = (s0 + s1) + (s2 + s3);
        }
        __syncthreads();
    }

    // expand: rewrite ALL rows directly from global (T is L2/L1-resident)
    {
        const int col = t * 4;   // this thread's 4 output columns
        #pragma unroll 1
        for (int r = 0; r < NROWS; r++) {
            const int b = r >> 13;   // r / Ssz
            ulonglong2 o; o.x = 0ull; o.y = 0ull;
            if (__ldcg(&g_rowflag[r])) {
                const u64* wr = &g_wdup[(size_t)r * Nsz];
                #pragma unroll
                for (int n = 0; n < Nsz; n++) {
                    u64 wv = __ldcg(&wr[n]);
                    ulonglong2 tv = *(const ulonglong2*)(g_T +
                        (size_t)(b * Nsz + n) * Dsz + col);
                    ffma2(o.x, wv, tv.x);
                    ffma2(o.y, wv, tv.y);
                }
                *(ulonglong2*)(out + (size_t)r * Dsz + col) = o;
            }
            // rows with flag==0 keep the prelude zeros (already exact)
        }
    }
}

extern "C" void kernel_launch(void* const* d_in, const int* in_sizes, int n_in,
                              void* d_out, int out_size) {
    const float* x        = (const float*)d_in[0];
    const float* centers  = (const float*)d_in[1];
    const float* scales   = (const float*)d_in[2];
    const float* amps     = (const float*)d_in[3];
    const float* w_value  = (const float*)d_in[4];
    const float* w_output = (const float*)d_in[5];
    float* out = (float*)d_out;

    k1<<<NBLK, 256>>>(x, centers, scales, amps, w_value, w_output, out);
}